// round 15
// baseline (speedup 1.0000x reference)
#include <cuda_runtime.h>

// FF_AtoB, FF_BtoA: [N=4, K*K=121, H=256, W=256] float32; K=11, pad=5.
// Output: scalar float loss.
#define NB   4
#define HH   256
#define WW   256
#define KK   11
#define PAD  5
#define HW   (HH * WW)           // 65536
#define NPIX (NB * HH * WW)      // 262144

// Pass2 smem tile (per direction): 14 halo rows x 272 float2 slots, quad-split:
//   halo col lc (ix = lc - PAD): subarray q = lc & 3, slot = q*68 + (lc >> 2).
#define SROW 272
#define SM_ROWS 14
#define SM_ELEMS (SM_ROWS * SROW)

// m1 per direction as float2 (2 MB each; both L2-resident).
__device__ float2 g_m1A[NPIX];   // filter(grid, FF_AtoB)
__device__ float2 g_m1B[NPIX];   // filter(grid, FF_BtoA)
__device__ float  g_part[512];
__device__ unsigned int g_done;  // zero-init; reset to 0 at end of every call

__device__ __forceinline__ float4 ldcs4(const float* p) {
    return __ldcs(reinterpret_cast<const float4*>(p));
}

// ---------------- Pass 1: fused dirs, float4 loads, dy-split 512-thr blocks --
// grid = 256 tiles (n = b>>6, 4 rows each). 512 threads: g = tid>>8 picks the
// dy half (0: dy 0-5, 1: dy 6-10); within a half: ty = row, 4 px/thread.
// Group 1 publishes partial m1 sums via smem; group 0 combines and stores.
__global__ __launch_bounds__(512, 2) void pass1_kernel(
    const float* __restrict__ ffA, const float* __restrict__ ffB)
{
    __shared__ float4 sp[1024];   // group-1 partials, [px][ty][i] layout

    const int tid = threadIdx.x;
    const int b   = blockIdx.x;
    const int n   = b >> 6;
    const int h0  = (b & 63) << 2;
    const int g   = tid >> 8;
    const int ty  = (tid >> 6) & 3;
    const int h   = h0 + ty;
    const int i   = tid & 63;
    const int wb  = i << 2;
    const float inv = 1.0f / 255.0f;

    // Column tables: t = dx + px in [0, 14), ix = wb + t - PAD
    float gxv[14], cf[14];
#pragma unroll
    for (int t = 0; t < 14; ++t) {
        int ix = wb + t - PAD;
        bool v = (unsigned)ix < (unsigned)WW;
        gxv[t] = v ? (float)ix * inv : 0.0f;
        cf[t]  = v ? 1.0f : 0.0f;
    }

    float m1ax[4] = {0,0,0,0}, m1ay[4] = {0,0,0,0};
    float m1bx[4] = {0,0,0,0}, m1by[4] = {0,0,0,0};

    const size_t base = (size_t)n * (121 * HW) + (size_t)h * WW + wb;
    const int dyLo = g ? 6 : 0;
    const int dyHi = g ? KK : 6;

#pragma unroll 1
    for (int dy = dyLo; dy < dyHi; ++dy) {
        const int  iy  = h + dy - PAD;
        const bool rv  = (unsigned)iy < (unsigned)HH;
        const float rf  = rv ? 1.0f : 0.0f;
        const float gy0 = rv ? (float)iy * inv : 0.0f;
        const size_t rowbase = base + (size_t)(dy * KK) * HW;
#pragma unroll
        for (int dx = 0; dx < KK; ++dx) {
            const float4 a4 = ldcs4(ffA + rowbase + (size_t)dx * HW);
            const float4 b4 = ldcs4(ffB + rowbase + (size_t)dx * HW);
            const float av[4] = {a4.x, a4.y, a4.z, a4.w};
            const float bv[4] = {b4.x, b4.y, b4.z, b4.w};
#pragma unroll
            for (int px = 0; px < 4; ++px) {
                const float xv = gxv[dx + px] * rf;
                const float yv = cf[dx + px] * gy0;
                m1ax[px] += av[px] * xv;
                m1ay[px] += av[px] * yv;
                m1bx[px] += bv[px] * xv;
                m1by[px] += bv[px] * yv;
            }
        }
    }

    // Combine the two dy-halves through smem ([px][ty][i]: conflict-free).
    if (g == 1) {
#pragma unroll
        for (int px = 0; px < 4; ++px)
            sp[px * 256 + ty * 64 + i] =
                make_float4(m1ax[px], m1ay[px], m1bx[px], m1by[px]);
    }
    __syncthreads();
    if (g == 0) {
        const int o = (n * HH + h) * WW + wb;
#pragma unroll
        for (int px = 0; px < 4; ++px) {
            const float4 p = sp[px * 256 + ty * 64 + i];
            g_m1A[o + px] = make_float2(m1ax[px] + p.x, m1ay[px] + p.y);
            g_m1B[o + px] = make_float2(m1bx[px] + p.z, m1by[px] + p.w);
        }
    }
}

// ---------------- Pass 2: direction-split, 4-row tiles, quad-split smem -----
// dir=0 (ABA): m2 = filter(m1A, FF_BtoA) -> weights ffB, data g_m1A
// dir=1 (BAB): m2 = filter(m1B, FF_AtoB) -> weights ffA, data g_m1B
__global__ __launch_bounds__(256, 4) void pass2_kernel(
    const float* __restrict__ ffA, const float* __restrict__ ffB,
    float* __restrict__ out)
{
    __shared__ float2 sm[SM_ELEMS];   // [14][SROW], quad-split per row

    const int tid = threadIdx.x;
    const int b   = blockIdx.x;
    const int dir = b >> 8;
    const int bb  = b & 255;
    const int n   = bb >> 6;
    const int h0  = (bb & 63) << 2;
    const float inv = 1.0f / 255.0f;

    const float*  __restrict__ ff = dir ? ffA : ffB;
    const float2* __restrict__ gm = dir ? g_m1B : g_m1A;

    // Cooperative halo fill (quad-split): rows iy = h0-5 .. h0+8.
    const int m1base = n * HW;
#pragma unroll 1
    for (int idx = tid; idx < SM_ELEMS; idx += 256) {
        const int r  = idx / SROW;
        const int s  = idx - r * SROW;
        const int q  = s / 68;
        const int ci = s - q * 68;
        const int lc = (ci << 2) + q;
        const int ix = lc - PAD;
        const int iy = h0 - PAD + r;
        float2 v = make_float2(0.0f, 0.0f);
        if ((unsigned)iy < (unsigned)HH && (unsigned)ix < (unsigned)WW)
            v = gm[m1base + iy * WW + ix];
        sm[idx] = v;
    }
    __syncthreads();

    const int ty = tid >> 6;
    const int h  = h0 + ty;
    const int i  = tid & 63;
    const int wb = i << 2;

    float m2x[4] = {0,0,0,0}, m2y[4] = {0,0,0,0};

    const size_t base = (size_t)n * (121 * HW) + (size_t)h * WW + wb;

#pragma unroll 1
    for (int dy = 0; dy < KK; ++dy) {
        const float2* se = sm + (ty + dy) * SROW;
        // Window: lc = wb + t = 4i + t, t in [0,14). Quad-split: subarray t&3,
        // slot i + (t>>2); consecutive lanes -> consecutive 8B slots.
        float2 w[14];
#pragma unroll
        for (int t = 0; t < 14; ++t) {
            const int off = (t & 3) * 68 + i + (t >> 2);
            w[t] = se[off];
        }

        const size_t rowbase = base + (size_t)(dy * KK) * HW;
#pragma unroll
        for (int dx = 0; dx < KK; ++dx) {
            const float4 f4 = ldcs4(ff + rowbase + (size_t)dx * HW);
            const float fv[4] = {f4.x, f4.y, f4.z, f4.w};
#pragma unroll
            for (int px = 0; px < 4; ++px) {
                const float2 m = w[dx + px];
                m2x[px] += fv[px] * m.x;
                m2y[px] += fv[px] * m.y;
            }
        }
    }

    const float gy = (float)h * inv;
    float acc = 0.0f;
#pragma unroll
    for (int px = 0; px < 4; ++px) {
        const float gx = (float)(wb + px) * inv;
        const float dx0 = gx - m2x[px], dy0 = gy - m2y[px];
        acc += sqrtf(dx0 * dx0 + dy0 * dy0);
    }

#pragma unroll
    for (int off = 16; off > 0; off >>= 1)
        acc += __shfl_down_sync(0xffffffffu, acc, off);
    __shared__ float sred[8];
    __shared__ bool s_last;
    if ((tid & 31) == 0) sred[tid >> 5] = acc;
    __syncthreads();
    if (tid == 0) {
        float t = 0.0f;
#pragma unroll
        for (int k = 0; k < 8; ++k) t += sred[k];
        g_part[blockIdx.x] = t;
        __threadfence();
        const unsigned int ticket = atomicAdd(&g_done, 1u);
        s_last = (ticket == gridDim.x - 1u);
    }
    __syncthreads();

    // Last block performs the deterministic final reduction over 512 partials.
    if (s_last) {
        float v = g_part[tid] + g_part[tid + 256];
#pragma unroll
        for (int off = 16; off > 0; off >>= 1)
            v += __shfl_down_sync(0xffffffffu, v, off);
        __shared__ float s2[8];
        if ((tid & 31) == 0) s2[tid >> 5] = v;
        __syncthreads();
        if (tid == 0) {
            float tot = 0.0f;
#pragma unroll
            for (int k = 0; k < 8; ++k) tot += s2[k];
            out[0] = tot * (1.0f / (float)NPIX);
            g_done = 0u;                 // reset for next graph replay
        }
    }
}

extern "C" void kernel_launch(void* const* d_in, const int* in_sizes, int n_in,
                              void* d_out, int out_size)
{
    (void)in_sizes; (void)n_in; (void)out_size;
    const float* ffA = (const float*)d_in[0];
    const float* ffB = (const float*)d_in[1];
    float* out = (float*)d_out;

    pass1_kernel<<<256, 512>>>(ffA, ffB);
    pass2_kernel<<<512, 256>>>(ffA, ffB, out);
}

// round 16
// speedup vs baseline: 1.1104x; 1.1104x over previous
#include <cuda_runtime.h>

// FF_AtoB, FF_BtoA: [N=4, K*K=121, H=256, W=256] float32; K=11, pad=5.
// Output: scalar float loss.
#define NB   4
#define HH   256
#define WW   256
#define KK   11
#define PAD  5
#define HW   (HH * WW)           // 65536
#define NPIX (NB * HH * WW)      // 262144

// Pass2 smem tile (per direction): 14 halo rows x 272 float2 slots, quad-split:
//   halo col lc (ix = lc - PAD): subarray q = lc & 3, slot = q*68 + (lc >> 2).
#define SROW 272
#define SM_ROWS 14
#define SM_ELEMS (SM_ROWS * SROW)

// m1 per direction as float2 (2 MB each; both L2-resident).
__device__ float2 g_m1A[NPIX];   // filter(grid, FF_AtoB)
__device__ float2 g_m1B[NPIX];   // filter(grid, FF_BtoA)
__device__ float  g_part[512];
__device__ unsigned int g_done;  // zero-init; reset to 0 at end of every call

__device__ __forceinline__ float4 ldcs4(const float* p) {
    return __ldcs(reinterpret_cast<const float4*>(p));
}

// ---------------- Pass 1: fused (pinned R7/R12 config), split float2 stores -
__global__ __launch_bounds__(256, 4) void pass1_kernel(
    const float* __restrict__ ffA, const float* __restrict__ ffB)
{
    const int tid = threadIdx.x;
    const int b   = blockIdx.x;
    const int n   = b >> 7;
    const int h   = ((b & 127) << 1) + (tid >> 7);
    const int wb  = (tid & 127) << 1;
    const float inv = 1.0f / 255.0f;

    float gxv[12], cf[12];
#pragma unroll
    for (int t = 0; t < 12; ++t) {
        int ix = wb + t - PAD;
        bool v = (unsigned)ix < (unsigned)WW;
        gxv[t] = v ? (float)ix * inv : 0.0f;
        cf[t]  = v ? 1.0f : 0.0f;
    }

    float m1ax[2] = {0,0}, m1ay[2] = {0,0};
    float m1bx[2] = {0,0}, m1by[2] = {0,0};

    const size_t base = (size_t)n * (121 * HW) + (size_t)h * WW + wb;

#pragma unroll 1
    for (int dy = 0; dy < KK; ++dy) {
        const int  iy  = h + dy - PAD;
        const bool rv  = (unsigned)iy < (unsigned)HH;
        const float rf  = rv ? 1.0f : 0.0f;
        const float gy0 = rv ? (float)iy * inv : 0.0f;
        const size_t rowbase = base + (size_t)(dy * KK) * HW;
#pragma unroll
        for (int dx = 0; dx < KK; ++dx) {
            const float2 a2 = *reinterpret_cast<const float2*>(ffA + rowbase + (size_t)dx * HW);
            const float2 b2 = *reinterpret_cast<const float2*>(ffB + rowbase + (size_t)dx * HW);
            const float av[2] = {a2.x, a2.y};
            const float bv[2] = {b2.x, b2.y};
#pragma unroll
            for (int px = 0; px < 2; ++px) {
                const float xv = gxv[dx + px] * rf;
                const float yv = cf[dx + px] * gy0;
                m1ax[px] += av[px] * xv;
                m1ay[px] += av[px] * yv;
                m1bx[px] += bv[px] * xv;
                m1by[px] += bv[px] * yv;
            }
        }
    }

    const int o = (n * HH + h) * WW + wb;
#pragma unroll
    for (int px = 0; px < 2; ++px) {
        g_m1A[o + px] = make_float2(m1ax[px], m1ay[px]);
        g_m1B[o + px] = make_float2(m1bx[px], m1by[px]);
    }
}

// ---------------- Pass 2: direction-split, 4-row tiles, quad-split smem -----
// dir=0 (ABA): m2 = filter(m1A, FF_BtoA) -> weights ffB, data g_m1A
// dir=1 (BAB): m2 = filter(m1B, FF_AtoB) -> weights ffA, data g_m1B
__global__ __launch_bounds__(256, 4) void pass2_kernel(
    const float* __restrict__ ffA, const float* __restrict__ ffB,
    float* __restrict__ out)
{
    __shared__ float2 sm[SM_ELEMS];   // [14][SROW], quad-split per row

    const int tid = threadIdx.x;
    const int b   = blockIdx.x;
    const int dir = b >> 8;
    const int bb  = b & 255;
    const int n   = bb >> 6;
    const int h0  = (bb & 63) << 2;
    const float inv = 1.0f / 255.0f;

    const float*  __restrict__ ff = dir ? ffA : ffB;
    const float2* __restrict__ gm = dir ? g_m1B : g_m1A;

    // Cooperative halo fill (quad-split): rows iy = h0-5 .. h0+8.
    const int m1base = n * HW;
#pragma unroll 1
    for (int idx = tid; idx < SM_ELEMS; idx += 256) {
        const int r  = idx / SROW;
        const int s  = idx - r * SROW;
        const int q  = s / 68;
        const int ci = s - q * 68;
        const int lc = (ci << 2) + q;
        const int ix = lc - PAD;
        const int iy = h0 - PAD + r;
        float2 v = make_float2(0.0f, 0.0f);
        if ((unsigned)iy < (unsigned)HH && (unsigned)ix < (unsigned)WW)
            v = gm[m1base + iy * WW + ix];
        sm[idx] = v;
    }
    __syncthreads();

    const int ty = tid >> 6;
    const int h  = h0 + ty;
    const int i  = tid & 63;
    const int wb = i << 2;

    float m2x[4] = {0,0,0,0}, m2y[4] = {0,0,0,0};

    const size_t base = (size_t)n * (121 * HW) + (size_t)h * WW + wb;

#pragma unroll 1
    for (int dy = 0; dy < KK; ++dy) {
        const float2* se = sm + (ty + dy) * SROW;
        // Window: lc = wb + t = 4i + t, t in [0,14). Quad-split: subarray t&3,
        // slot i + (t>>2); consecutive lanes -> consecutive 8B slots.
        float2 w[14];
#pragma unroll
        for (int t = 0; t < 14; ++t) {
            const int off = (t & 3) * 68 + i + (t >> 2);
            w[t] = se[off];
        }

        const size_t rowbase = base + (size_t)(dy * KK) * HW;
#pragma unroll
        for (int dx = 0; dx < KK; ++dx) {
            const float4 f4 = ldcs4(ff + rowbase + (size_t)dx * HW);
            const float fv[4] = {f4.x, f4.y, f4.z, f4.w};
#pragma unroll
            for (int px = 0; px < 4; ++px) {
                const float2 m = w[dx + px];
                m2x[px] += fv[px] * m.x;
                m2y[px] += fv[px] * m.y;
            }
        }
    }

    const float gy = (float)h * inv;
    float acc = 0.0f;
#pragma unroll
    for (int px = 0; px < 4; ++px) {
        const float gx = (float)(wb + px) * inv;
        const float dx0 = gx - m2x[px], dy0 = gy - m2y[px];
        acc += sqrtf(dx0 * dx0 + dy0 * dy0);
    }

#pragma unroll
    for (int off = 16; off > 0; off >>= 1)
        acc += __shfl_down_sync(0xffffffffu, acc, off);
    __shared__ float sred[8];
    __shared__ bool s_last;
    if ((tid & 31) == 0) sred[tid >> 5] = acc;
    __syncthreads();
    if (tid == 0) {
        float t = 0.0f;
#pragma unroll
        for (int k = 0; k < 8; ++k) t += sred[k];
        g_part[blockIdx.x] = t;
        __threadfence();
        const unsigned int ticket = atomicAdd(&g_done, 1u);
        s_last = (ticket == gridDim.x - 1u);
    }
    __syncthreads();

    // Last block performs the deterministic final reduction over 512 partials.
    if (s_last) {
        float v = g_part[tid] + g_part[tid + 256];
#pragma unroll
        for (int off = 16; off > 0; off >>= 1)
            v += __shfl_down_sync(0xffffffffu, v, off);
        __shared__ float s2[8];
        if ((tid & 31) == 0) s2[tid >> 5] = v;
        __syncthreads();
        if (tid == 0) {
            float tot = 0.0f;
#pragma unroll
            for (int k = 0; k < 8; ++k) tot += s2[k];
            out[0] = tot * (1.0f / (float)NPIX);
            g_done = 0u;                 // reset for next graph replay
        }
    }
}

extern "C" void kernel_launch(void* const* d_in, const int* in_sizes, int n_in,
                              void* d_out, int out_size)
{
    (void)in_sizes; (void)n_in; (void)out_size;
    const float* ffA = (const float*)d_in[0];
    const float* ffB = (const float*)d_in[1];
    float* out = (float*)d_out;

    pass1_kernel<<<512, 256>>>(ffA, ffB);
    pass2_kernel<<<512, 256>>>(ffA, ffB, out);
}